// round 1
// baseline (speedup 1.0000x reference)
#include <cuda_runtime.h>
#include <cuda_bf16.h>
#include <math_constants.h>

#define N_NODES   10000
#define N_EDGES   160000
#define E_TOT     170000      // edges + self loops
#define D_MODEL   128
#define NHEAD     8
#define HEAD_DIM  16
#define NUM_LAYERS 7
#define CHUNK     10          // NUM_LABELS + nchunks = 2 + 8
#define NUM_LABELS 2
#define NEG_SLOPE 0.2f

// ---------------- device scratch (no allocation allowed) ----------------
__device__ float g_bufA[N_NODES * D_MODEL];
__device__ float g_bufB[N_NODES * D_MODEL];
__device__ float g_xl[N_NODES * D_MODEL];
__device__ float g_xr[N_NODES * D_MODEL];
__device__ float g_e[E_TOT * NHEAD];
__device__ float g_emax[N_NODES * NHEAD];
__device__ float g_denom[N_NODES * NHEAD];
__device__ int   g_src[E_TOT];
__device__ int   g_dst[E_TOT];
__device__ int   g_is64;

// ---------------- helpers ----------------
__device__ __forceinline__ void atomicMaxF(float* addr, float v) {
    if (v >= 0.0f) atomicMax((int*)addr, __float_as_int(v));
    else           atomicMin((unsigned int*)addr, __float_as_uint(v));
}

__device__ __forceinline__ void red_add4(float* p, float a, float b, float c, float d) {
    asm volatile("red.global.add.v4.f32 [%0], {%1,%2,%3,%4};"
                 :: "l"(p), "f"(a), "f"(b), "f"(c), "f"(d) : "memory");
}

// ---------------- dtype detection for edge_index (int32 vs int64) --------
__global__ void k_detect(const int* __restrict__ e32) {
    __shared__ int nz;
    if (threadIdx.x == 0) nz = 0;
    __syncthreads();
    // If int64 little-endian, every odd 32-bit word is a zero high-word.
    for (int i = threadIdx.x; i < 1024; i += blockDim.x)
        if (e32[2 * i + 1] != 0) nz = 1;
    __syncthreads();
    if (threadIdx.x == 0) g_is64 = (nz == 0) ? 1 : 0;
}

__global__ void k_extract(const int* __restrict__ e32) {
    int t = blockIdx.x * blockDim.x + threadIdx.x;
    if (t >= E_TOT) return;
    if (t < N_EDGES) {
        if (g_is64) {
            g_src[t] = e32[2 * t];                       // low word of int64
            g_dst[t] = e32[2 * (N_EDGES + t)];
        } else {
            g_src[t] = e32[t];
            g_dst[t] = e32[N_EDGES + t];
        }
    } else {
        int n = t - N_EDGES;                              // self loop
        g_src[t] = n;
        g_dst[t] = n;
    }
}

// ---------------- per-layer init: out=bias, emax=-inf, denom=0 -----------
__global__ void k_init(float* __restrict__ out, const float* __restrict__ bias) {
    int t = blockIdx.x * blockDim.x + threadIdx.x;
    if (t < N_NODES * D_MODEL) out[t] = bias[t & 127];
    if (t < N_NODES * NHEAD) {
        g_emax[t]  = __int_as_float(0xFF800000);          // -inf
        g_denom[t] = 0.0f;
    }
}

// ---------------- fused GEMM: xl = X@Wl + bl ; xr = X@Wr + br -------------
// blockIdx.y: 0 -> (Wl,bl,g_xl) ; 1 -> (Wr,br,g_xr)
// tile: 64 rows x 128 cols, BK=16, 256 threads, 8x4 per-thread micro-tile
__global__ void __launch_bounds__(256) k_gemm(
    const float* __restrict__ X,
    const float* __restrict__ Wl, const float* __restrict__ bl,
    const float* __restrict__ Wr, const float* __restrict__ br)
{
    const float* W = blockIdx.y ? Wr : Wl;
    const float* b = blockIdx.y ? br : bl;
    float* out = blockIdx.y ? g_xr : g_xl;

    __shared__ float As[64][16];
    __shared__ float Bs[16][128];

    const int tid  = threadIdx.x;
    const int row0 = blockIdx.x * 64;
    const int trow = tid >> 5;    // 0..7
    const int tcol = tid & 31;    // 0..31

    float acc[8][4];
    #pragma unroll
    for (int i = 0; i < 8; i++)
        #pragma unroll
        for (int j = 0; j < 4; j++) acc[i][j] = 0.0f;

    for (int k0 = 0; k0 < 128; k0 += 16) {
        // load A tile: 64x16 = 256 float4
        {
            int r  = tid >> 2;
            int c4 = (tid & 3) * 4;
            int gr = row0 + r;
            float4 v = (gr < N_NODES)
                ? *(const float4*)(X + gr * 128 + k0 + c4)
                : make_float4(0.f, 0.f, 0.f, 0.f);
            As[r][c4 + 0] = v.x; As[r][c4 + 1] = v.y;
            As[r][c4 + 2] = v.z; As[r][c4 + 3] = v.w;
        }
        // load B tile: 16x128 = 512 float4, 2 per thread
        #pragma unroll
        for (int f = tid; f < 512; f += 256) {
            int r  = f >> 5;
            int c4 = (f & 31) * 4;
            *(float4*)(&Bs[r][c4]) = *(const float4*)(W + (k0 + r) * 128 + c4);
        }
        __syncthreads();

        #pragma unroll
        for (int k = 0; k < 16; k++) {
            float a[8], bb[4];
            #pragma unroll
            for (int i = 0; i < 8; i++) a[i] = As[trow * 8 + i][k];
            #pragma unroll
            for (int j = 0; j < 4; j++) bb[j] = Bs[k][tcol * 4 + j];
            #pragma unroll
            for (int i = 0; i < 8; i++)
                #pragma unroll
                for (int j = 0; j < 4; j++)
                    acc[i][j] = fmaf(a[i], bb[j], acc[i][j]);
        }
        __syncthreads();
    }

    #pragma unroll
    for (int i = 0; i < 8; i++) {
        int gr = row0 + trow * 8 + i;
        if (gr < N_NODES) {
            int c = tcol * 4;
            float4 v;
            v.x = acc[i][0] + b[c + 0];
            v.y = acc[i][1] + b[c + 1];
            v.z = acc[i][2] + b[c + 2];
            v.w = acc[i][3] + b[c + 3];
            *(float4*)(out + gr * 128 + c) = v;
        }
    }
}

// ---------------- edge score: e = att . leaky_relu(xl[src]+xr[dst]) ------
__global__ void k_score(const float* __restrict__ att) {
    int t = blockIdx.x * blockDim.x + threadIdx.x;
    if (t >= E_TOT * NHEAD) return;
    int eidx = t >> 3;
    int h    = t & 7;
    int s = g_src[eidx];
    int d = g_dst[eidx];
    const float4* xl4 = (const float4*)(g_xl + s * 128 + h * 16);
    const float4* xr4 = (const float4*)(g_xr + d * 128 + h * 16);
    const float4* a4  = (const float4*)(att + h * 16);
    float e = 0.0f;
    #pragma unroll
    for (int i = 0; i < 4; i++) {
        float4 l = xl4[i], r = xr4[i], a = a4[i];
        float z;
        z = l.x + r.x; z = z > 0.f ? z : NEG_SLOPE * z; e = fmaf(z, a.x, e);
        z = l.y + r.y; z = z > 0.f ? z : NEG_SLOPE * z; e = fmaf(z, a.y, e);
        z = l.z + r.z; z = z > 0.f ? z : NEG_SLOPE * z; e = fmaf(z, a.z, e);
        z = l.w + r.w; z = z > 0.f ? z : NEG_SLOPE * z; e = fmaf(z, a.w, e);
    }
    g_e[t] = e;
    atomicMaxF(&g_emax[d * NHEAD + h], e);
}

// ---------------- exp + segment sum --------------------------------------
__global__ void k_exp() {
    int t = blockIdx.x * blockDim.x + threadIdx.x;
    if (t >= E_TOT * NHEAD) return;
    int eidx = t >> 3;
    int h    = t & 7;
    int d = g_dst[eidx];
    float ex = __expf(g_e[t] - g_emax[d * NHEAD + h]);
    g_e[t] = ex;
    atomicAdd(&g_denom[d * NHEAD + h], ex);
}

// ---------------- aggregate: out[dst] += alpha * xl[src] -----------------
__global__ void k_agg(float* __restrict__ out) {
    int t = blockIdx.x * blockDim.x + threadIdx.x;
    if (t >= E_TOT * NHEAD) return;
    int eidx = t >> 3;
    int h    = t & 7;
    int s = g_src[eidx];
    int d = g_dst[eidx];
    float alpha = g_e[t] / (g_denom[d * NHEAD + h] + 1e-16f);
    const float4* xl4 = (const float4*)(g_xl + s * 128 + h * 16);
    float* o = out + d * 128 + h * 16;
    #pragma unroll
    for (int i = 0; i < 4; i++) {
        float4 v = xl4[i];
        red_add4(o + i * 4, alpha * v.x, alpha * v.y, alpha * v.z, alpha * v.w);
    }
}

// ---------------- final head: out[c,l] = x[c*10+l] . w + b ---------------
__global__ void k_head(const float* __restrict__ xin, const float* __restrict__ w,
                       const float* __restrict__ bh, float* __restrict__ out)
{
    int gt   = blockIdx.x * blockDim.x + threadIdx.x;
    int warp = gt >> 5;
    int lane = gt & 31;
    if (warp >= (N_NODES / CHUNK) * NUM_LABELS) return;
    int c = warp / NUM_LABELS;
    int l = warp % NUM_LABELS;
    const float* row = xin + (c * CHUNK + l) * 128;
    float s = 0.0f;
    #pragma unroll
    for (int i = lane; i < 128; i += 32) s = fmaf(row[i], w[i], s);
    #pragma unroll
    for (int o = 16; o; o >>= 1) s += __shfl_down_sync(0xffffffffu, s, o);
    if (lane == 0) out[warp] = s + bh[0];
}

// ---------------- launch ---------------------------------------------------
extern "C" void kernel_launch(void* const* d_in, const int* in_sizes, int n_in,
                              void* d_out, int out_size)
{
    const float* x    = (const float*)d_in[0];
    const int*   eidx = (const int*)  d_in[1];
    // d_in[2] = nchunks (fixed = 8, chunk = 10; hardcoded)
    const float* Wl   = (const float*)d_in[3];
    const float* bl   = (const float*)d_in[4];
    const float* Wr   = (const float*)d_in[5];
    const float* br   = (const float*)d_in[6];
    const float* att  = (const float*)d_in[7];
    const float* bias = (const float*)d_in[8];
    const float* wh   = (const float*)d_in[9];
    const float* bh   = (const float*)d_in[10];
    float* out = (float*)d_out;

    float *bufA = nullptr, *bufB = nullptr;
    cudaGetSymbolAddress((void**)&bufA, g_bufA);
    cudaGetSymbolAddress((void**)&bufB, g_bufB);

    k_detect<<<1, 256>>>(eidx);
    k_extract<<<(E_TOT + 255) / 256, 256>>>(eidx);

    const float* cur = x;
    const int EH = E_TOT * NHEAD;
    for (int l = 0; l < NUM_LAYERS; l++) {
        float* nxt = (l & 1) ? bufB : bufA;
        k_init<<<(N_NODES * D_MODEL + 255) / 256, 256>>>(nxt, bias + l * D_MODEL);
        dim3 gg((N_NODES + 63) / 64, 2);
        k_gemm<<<gg, 256>>>(cur,
                            Wl + l * D_MODEL * D_MODEL, bl + l * D_MODEL,
                            Wr + l * D_MODEL * D_MODEL, br + l * D_MODEL);
        k_score<<<(EH + 255) / 256, 256>>>(att + l * NHEAD * HEAD_DIM);
        k_exp<<<(EH + 255) / 256, 256>>>();
        k_agg<<<(EH + 255) / 256, 256>>>(nxt);
        cur = nxt;
    }
    int nwarp = (N_NODES / CHUNK) * NUM_LABELS;  // 2000
    k_head<<<(nwarp * 32 + 255) / 256, 256>>>(cur, wh, bh, out);
}

// round 2
// speedup vs baseline: 1.4245x; 1.4245x over previous
#include <cuda_runtime.h>
#include <cuda_bf16.h>
#include <math_constants.h>

#define N_NODES   10000
#define N_EDGES   160000
#define E_TOT     170000      // edges + self loops
#define D_MODEL   128
#define NHEAD     8
#define HEAD_DIM  16
#define NUM_LAYERS 7
#define CHUNK     10          // NUM_LABELS + nchunks = 2 + 8
#define NUM_LABELS 2
#define NEG_SLOPE 0.2f

// ---------------- device scratch (no allocation allowed) ----------------
__device__ float g_bufA[N_NODES * D_MODEL];
__device__ float g_bufB[N_NODES * D_MODEL];
__device__ float g_xl[N_NODES * D_MODEL];
__device__ float g_xr[N_NODES * D_MODEL];
__device__ int   g_src[E_TOT];
__device__ int   g_dst[E_TOT];
__device__ int   g_cnt[N_NODES];
__device__ int   g_start[N_NODES + 1];
__device__ int   g_cursor[N_NODES];
__device__ int   g_csr[E_TOT];       // src node ids grouped by dst
__device__ int   g_is64;

// ---------------- dtype detection for edge_index (int32 vs int64) --------
__global__ void k_detect(const int* __restrict__ e32) {
    __shared__ int nz;
    if (threadIdx.x == 0) nz = 0;
    __syncthreads();
    for (int i = threadIdx.x; i < 1024; i += blockDim.x)
        if (e32[2 * i + 1] != 0) nz = 1;
    __syncthreads();
    if (threadIdx.x == 0) g_is64 = (nz == 0) ? 1 : 0;
}

__global__ void k_zero_cnt() {
    int t = blockIdx.x * blockDim.x + threadIdx.x;
    if (t < N_NODES) g_cnt[t] = 0;
}

// build src/dst (incl self loops) + histogram of dst
__global__ void k_extract(const int* __restrict__ e32) {
    int t = blockIdx.x * blockDim.x + threadIdx.x;
    if (t >= E_TOT) return;
    int s, d;
    if (t < N_EDGES) {
        if (g_is64) {
            s = e32[2 * t];
            d = e32[2 * (N_EDGES + t)];
        } else {
            s = e32[t];
            d = e32[N_EDGES + t];
        }
    } else {
        s = t - N_EDGES;
        d = s;
    }
    g_src[t] = s;
    g_dst[t] = d;
    atomicAdd(&g_cnt[d], 1);
}

// exclusive scan of g_cnt -> g_start / g_cursor. one block, 1024 threads.
__global__ void __launch_bounds__(1024) k_scan() {
    __shared__ int ss[1024];
    const int t = threadIdx.x;
    const int base = t * 10;
    int local[10];
    int sum = 0;
    #pragma unroll
    for (int i = 0; i < 10; i++) {
        int idx = base + i;
        local[i] = (idx < N_NODES) ? g_cnt[idx] : 0;
        sum += local[i];
    }
    ss[t] = sum;
    __syncthreads();
    // Hillis-Steele inclusive scan
    for (int off = 1; off < 1024; off <<= 1) {
        int v = (t >= off) ? ss[t - off] : 0;
        __syncthreads();
        ss[t] += v;
        __syncthreads();
    }
    int run = (t > 0) ? ss[t - 1] : 0;   // exclusive prefix of this thread's chunk
    #pragma unroll
    for (int i = 0; i < 10; i++) {
        int idx = base + i;
        if (idx < N_NODES) {
            g_start[idx]  = run;
            g_cursor[idx] = run;
        }
        run += local[i];
    }
    if (t == 0) g_start[N_NODES] = E_TOT;
}

__global__ void k_scatter() {
    int t = blockIdx.x * blockDim.x + threadIdx.x;
    if (t >= E_TOT) return;
    int d = g_dst[t];
    int pos = atomicAdd(&g_cursor[d], 1);
    g_csr[pos] = g_src[t];
}

// ---------------- fused GEMM: xl = X@Wl + bl ; xr = X@Wr + br -------------
// blockIdx.y: 0 -> (Wl,bl,g_xl) ; 1 -> (Wr,br,g_xr)
// 128x128 tile, BK=16, 256 threads, 8x8 micro-tile
__global__ void __launch_bounds__(256) k_gemm(
    const float* __restrict__ X,
    const float* __restrict__ Wl, const float* __restrict__ bl,
    const float* __restrict__ Wr, const float* __restrict__ br)
{
    const float* W = blockIdx.y ? Wr : Wl;
    const float* b = blockIdx.y ? br : bl;
    float* out = blockIdx.y ? g_xr : g_xl;

    __shared__ float As[16][132];   // transposed A tile, padded
    __shared__ float Bs[16][128];

    const int tid  = threadIdx.x;
    const int tx   = tid & 15;      // 0..15 -> output cols tx*8
    const int ty   = tid >> 4;      // 0..15 -> output rows ty*8
    const int row0 = blockIdx.x * 128;

    float acc[8][8];
    #pragma unroll
    for (int i = 0; i < 8; i++)
        #pragma unroll
        for (int j = 0; j < 8; j++) acc[i][j] = 0.0f;

    for (int k0 = 0; k0 < 128; k0 += 16) {
        // A tile: 128 rows x 16 k  (512 float4, 2 per thread), stored transposed
        #pragma unroll
        for (int f = tid; f < 512; f += 256) {
            int r   = f >> 2;
            int kc4 = (f & 3) * 4;
            int gr  = row0 + r;
            float4 v = (gr < N_NODES)
                ? *(const float4*)(X + gr * 128 + k0 + kc4)
                : make_float4(0.f, 0.f, 0.f, 0.f);
            As[kc4 + 0][r] = v.x;
            As[kc4 + 1][r] = v.y;
            As[kc4 + 2][r] = v.z;
            As[kc4 + 3][r] = v.w;
        }
        // B tile: 16 k x 128 cols (512 float4, 2 per thread)
        #pragma unroll
        for (int f = tid; f < 512; f += 256) {
            int r  = f >> 5;
            int c4 = (f & 31) * 4;
            *(float4*)(&Bs[r][c4]) = *(const float4*)(W + (k0 + r) * 128 + c4);
        }
        __syncthreads();

        #pragma unroll
        for (int k = 0; k < 16; k++) {
            float a[8], bb[8];
            *(float4*)(a + 0) = *(const float4*)(&As[k][ty * 8 + 0]);
            *(float4*)(a + 4) = *(const float4*)(&As[k][ty * 8 + 4]);
            *(float4*)(bb + 0) = *(const float4*)(&Bs[k][tx * 8 + 0]);
            *(float4*)(bb + 4) = *(const float4*)(&Bs[k][tx * 8 + 4]);
            #pragma unroll
            for (int i = 0; i < 8; i++)
                #pragma unroll
                for (int j = 0; j < 8; j++)
                    acc[i][j] = fmaf(a[i], bb[j], acc[i][j]);
        }
        __syncthreads();
    }

    #pragma unroll
    for (int i = 0; i < 8; i++) {
        int gr = row0 + ty * 8 + i;
        if (gr < N_NODES) {
            int c = tx * 8;
            float4 v0, v1;
            v0.x = acc[i][0] + b[c + 0];
            v0.y = acc[i][1] + b[c + 1];
            v0.z = acc[i][2] + b[c + 2];
            v0.w = acc[i][3] + b[c + 3];
            v1.x = acc[i][4] + b[c + 4];
            v1.y = acc[i][5] + b[c + 5];
            v1.z = acc[i][6] + b[c + 6];
            v1.w = acc[i][7] + b[c + 7];
            *(float4*)(out + gr * 128 + c + 0) = v0;
            *(float4*)(out + gr * 128 + c + 4) = v1;
        }
    }
}

// ---------------- fused edge kernel: online softmax + aggregate ----------
// one block (128 threads) per node; thread t -> head t/16, dim t%16
__global__ void __launch_bounds__(128) k_layer(
    const float* __restrict__ att, const float* __restrict__ bias,
    float* __restrict__ out)
{
    const int n = blockIdx.x;
    const int t = threadIdx.x;

    const float xr_v  = g_xr[n * 128 + t];
    const float att_v = att[t];

    const int beg = g_start[n];
    const int end = g_start[n + 1];   // >= beg+1 (self loop guarantees)

    float m   = __int_as_float(0xFF800000);  // -inf
    float s   = 0.0f;
    float acc = 0.0f;

    // software pipeline: prefetch first edge
    int   src = g_csr[beg];
    float v   = g_xl[src * 128 + t];

    for (int e = beg; e < end; e++) {
        float vcur = v;
        if (e + 1 < end) {
            int s2 = g_csr[e + 1];
            v = g_xl[s2 * 128 + t];
        }
        // e_h = att . leaky_relu(xl + xr) over the 16 dims of this head
        float z = vcur + xr_v;
        z = (z > 0.f) ? z : NEG_SLOPE * z;
        float w = z * att_v;
        w += __shfl_xor_sync(0xffffffffu, w, 8);
        w += __shfl_xor_sync(0xffffffffu, w, 4);
        w += __shfl_xor_sync(0xffffffffu, w, 2);
        w += __shfl_xor_sync(0xffffffffu, w, 1);
        // online softmax update; exp(-|d|) serves as both p and scale
        float d  = w - m;
        float q  = __expf(-fabsf(d));
        bool  nm = (d > 0.f);
        float p     = nm ? 1.0f : q;
        float scale = nm ? q : 1.0f;
        s   = fmaf(s, scale, p);
        acc = fmaf(acc, scale, p * vcur);
        m   = fmaxf(m, w);
    }

    out[n * 128 + t] = acc / (s + 1e-16f) + bias[t];
}

// ---------------- final head: out[c,l] = x[c*10+l] . w + b ---------------
__global__ void k_head(const float* __restrict__ xin, const float* __restrict__ w,
                       const float* __restrict__ bh, float* __restrict__ out)
{
    int gt   = blockIdx.x * blockDim.x + threadIdx.x;
    int warp = gt >> 5;
    int lane = gt & 31;
    if (warp >= (N_NODES / CHUNK) * NUM_LABELS) return;
    int c = warp / NUM_LABELS;
    int l = warp % NUM_LABELS;
    const float* row = xin + (c * CHUNK + l) * 128;
    float s = 0.0f;
    #pragma unroll
    for (int i = lane; i < 128; i += 32) s = fmaf(row[i], w[i], s);
    #pragma unroll
    for (int o = 16; o; o >>= 1) s += __shfl_down_sync(0xffffffffu, s, o);
    if (lane == 0) out[warp] = s + bh[0];
}

// ---------------- launch ---------------------------------------------------
extern "C" void kernel_launch(void* const* d_in, const int* in_sizes, int n_in,
                              void* d_out, int out_size)
{
    const float* x    = (const float*)d_in[0];
    const int*   eidx = (const int*)  d_in[1];
    // d_in[2] = nchunks (fixed = 8, chunk = 10; hardcoded)
    const float* Wl   = (const float*)d_in[3];
    const float* bl   = (const float*)d_in[4];
    const float* Wr   = (const float*)d_in[5];
    const float* br   = (const float*)d_in[6];
    const float* att  = (const float*)d_in[7];
    const float* bias = (const float*)d_in[8];
    const float* wh   = (const float*)d_in[9];
    const float* bh   = (const float*)d_in[10];
    float* out = (float*)d_out;

    float *bufA = nullptr, *bufB = nullptr;
    cudaGetSymbolAddress((void**)&bufA, g_bufA);
    cudaGetSymbolAddress((void**)&bufB, g_bufB);

    // CSR build (once per launch)
    k_detect<<<1, 256>>>(eidx);
    k_zero_cnt<<<(N_NODES + 255) / 256, 256>>>();
    k_extract<<<(E_TOT + 255) / 256, 256>>>(eidx);
    k_scan<<<1, 1024>>>();
    k_scatter<<<(E_TOT + 255) / 256, 256>>>();

    const float* cur = x;
    for (int l = 0; l < NUM_LAYERS; l++) {
        float* nxt = (l & 1) ? bufB : bufA;
        dim3 gg((N_NODES + 127) / 128, 2);
        k_gemm<<<gg, 256>>>(cur,
                            Wl + l * D_MODEL * D_MODEL, bl + l * D_MODEL,
                            Wr + l * D_MODEL * D_MODEL, br + l * D_MODEL);
        k_layer<<<N_NODES, 128>>>(att + l * NHEAD * HEAD_DIM,
                                  bias + l * D_MODEL, nxt);
        cur = nxt;
    }
    int nwarp = (N_NODES / CHUNK) * NUM_LABELS;  // 2000
    k_head<<<(nwarp * 32 + 255) / 256, 256>>>(cur, wh, bh, out);
}

// round 3
// speedup vs baseline: 1.7728x; 1.2445x over previous
#include <cuda_runtime.h>
#include <cuda_bf16.h>
#include <math_constants.h>

#define N_NODES   10000
#define N_EDGES   160000
#define E_TOT     170000      // edges + self loops
#define D_MODEL   128
#define NHEAD     8
#define HEAD_DIM  16
#define NUM_LAYERS 7
#define CHUNK     10          // NUM_LABELS + nchunks = 2 + 8
#define NUM_LABELS 2
#define NEG_SLOPE 0.2f

// ---------------- device scratch (no allocation allowed) ----------------
__device__ float g_bufA[N_NODES * D_MODEL];
__device__ float g_bufB[N_NODES * D_MODEL];
__device__ float g_xl[N_NODES * D_MODEL];
__device__ float g_xr[N_NODES * D_MODEL];
__device__ int   g_src[E_TOT];
__device__ int   g_dst[E_TOT];
__device__ int   g_cnt[N_NODES];
__device__ int   g_start[N_NODES + 1];
__device__ int   g_cursor[N_NODES];
__device__ int   g_csr[E_TOT];       // src node ids grouped by dst
__device__ int   g_is64;

// ------------- dtype detect (int32 vs int64) + zero counters -------------
__global__ void k_detect_zero(const int* __restrict__ e32) {
    int t = blockIdx.x * blockDim.x + threadIdx.x;
    if (t < N_NODES) g_cnt[t] = 0;
    if (blockIdx.x == 0) {
        __shared__ int nz;
        if (threadIdx.x == 0) nz = 0;
        __syncthreads();
        for (int i = threadIdx.x; i < 1024; i += blockDim.x)
            if (e32[2 * i + 1] != 0) nz = 1;
        __syncthreads();
        if (threadIdx.x == 0) g_is64 = (nz == 0) ? 1 : 0;
    }
}

// build src/dst (incl self loops) + histogram of dst
__global__ void k_extract(const int* __restrict__ e32) {
    int t = blockIdx.x * blockDim.x + threadIdx.x;
    if (t >= E_TOT) return;
    int s, d;
    if (t < N_EDGES) {
        if (g_is64) {
            s = e32[2 * t];
            d = e32[2 * (N_EDGES + t)];
        } else {
            s = e32[t];
            d = e32[N_EDGES + t];
        }
    } else {
        s = t - N_EDGES;
        d = s;
    }
    g_src[t] = s;
    g_dst[t] = d;
    atomicAdd(&g_cnt[d], 1);
}

// exclusive scan of g_cnt -> g_start / g_cursor. one block, 1024 threads,
// warp-shuffle two-level scan (2 barriers).
__global__ void __launch_bounds__(1024) k_scan() {
    __shared__ int warpsum[32];
    const int t    = threadIdx.x;
    const int lane = t & 31;
    const int warp = t >> 5;
    const int base = t * 10;

    int local[10];
    int sum = 0;
    #pragma unroll
    for (int i = 0; i < 10; i++) {
        int idx = base + i;
        local[i] = (idx < N_NODES) ? g_cnt[idx] : 0;
        sum += local[i];
    }
    // warp inclusive scan of sum
    int incl = sum;
    #pragma unroll
    for (int off = 1; off < 32; off <<= 1) {
        int v = __shfl_up_sync(0xffffffffu, incl, off);
        if (lane >= off) incl += v;
    }
    if (lane == 31) warpsum[warp] = incl;
    __syncthreads();
    if (warp == 0) {
        int w = warpsum[lane];
        int wi = w;
        #pragma unroll
        for (int off = 1; off < 32; off <<= 1) {
            int v = __shfl_up_sync(0xffffffffu, wi, off);
            if (lane >= off) wi += v;
        }
        warpsum[lane] = wi - w;   // exclusive
    }
    __syncthreads();
    int run = warpsum[warp] + (incl - sum);   // exclusive prefix of this thread's chunk
    #pragma unroll
    for (int i = 0; i < 10; i++) {
        int idx = base + i;
        if (idx < N_NODES) {
            g_start[idx]  = run;
            g_cursor[idx] = run;
        }
        run += local[i];
    }
    if (t == 0) g_start[N_NODES] = E_TOT;
}

__global__ void k_scatter() {
    int t = blockIdx.x * blockDim.x + threadIdx.x;
    if (t >= E_TOT) return;
    int d = g_dst[t];
    int pos = atomicAdd(&g_cursor[d], 1);
    g_csr[pos] = g_src[t];
}

// ---------------- fused GEMM: xl = X@Wl + bl ; xr = X@Wr + br -------------
// blockIdx.y: 0 -> (Wl,bl,g_xl) ; 1 -> (Wr,br,g_xr)
// 128x128 tile, BK=16, 256 threads, 8x8 micro-tile
__global__ void __launch_bounds__(256) k_gemm(
    const float* __restrict__ X,
    const float* __restrict__ Wl, const float* __restrict__ bl,
    const float* __restrict__ Wr, const float* __restrict__ br)
{
    const float* W = blockIdx.y ? Wr : Wl;
    const float* b = blockIdx.y ? br : bl;
    float* out = blockIdx.y ? g_xr : g_xl;

    __shared__ float As[16][132];   // transposed A tile, padded
    __shared__ float Bs[16][128];

    const int tid  = threadIdx.x;
    const int tx   = tid & 15;      // 0..15 -> output cols tx*8
    const int ty   = tid >> 4;      // 0..15 -> output rows ty*8
    const int row0 = blockIdx.x * 128;

    float acc[8][8];
    #pragma unroll
    for (int i = 0; i < 8; i++)
        #pragma unroll
        for (int j = 0; j < 8; j++) acc[i][j] = 0.0f;

    for (int k0 = 0; k0 < 128; k0 += 16) {
        #pragma unroll
        for (int f = tid; f < 512; f += 256) {
            int r   = f >> 2;
            int kc4 = (f & 3) * 4;
            int gr  = row0 + r;
            float4 v = (gr < N_NODES)
                ? *(const float4*)(X + gr * 128 + k0 + kc4)
                : make_float4(0.f, 0.f, 0.f, 0.f);
            As[kc4 + 0][r] = v.x;
            As[kc4 + 1][r] = v.y;
            As[kc4 + 2][r] = v.z;
            As[kc4 + 3][r] = v.w;
        }
        #pragma unroll
        for (int f = tid; f < 512; f += 256) {
            int r  = f >> 5;
            int c4 = (f & 31) * 4;
            *(float4*)(&Bs[r][c4]) = *(const float4*)(W + (k0 + r) * 128 + c4);
        }
        __syncthreads();

        #pragma unroll
        for (int k = 0; k < 16; k++) {
            float a[8], bb[8];
            *(float4*)(a + 0) = *(const float4*)(&As[k][ty * 8 + 0]);
            *(float4*)(a + 4) = *(const float4*)(&As[k][ty * 8 + 4]);
            *(float4*)(bb + 0) = *(const float4*)(&Bs[k][tx * 8 + 0]);
            *(float4*)(bb + 4) = *(const float4*)(&Bs[k][tx * 8 + 4]);
            #pragma unroll
            for (int i = 0; i < 8; i++)
                #pragma unroll
                for (int j = 0; j < 8; j++)
                    acc[i][j] = fmaf(a[i], bb[j], acc[i][j]);
        }
        __syncthreads();
    }

    #pragma unroll
    for (int i = 0; i < 8; i++) {
        int gr = row0 + ty * 8 + i;
        if (gr < N_NODES) {
            int c = tx * 8;
            float4 v0, v1;
            v0.x = acc[i][0] + b[c + 0];
            v0.y = acc[i][1] + b[c + 1];
            v0.z = acc[i][2] + b[c + 2];
            v0.w = acc[i][3] + b[c + 3];
            v1.x = acc[i][4] + b[c + 4];
            v1.y = acc[i][5] + b[c + 5];
            v1.z = acc[i][6] + b[c + 6];
            v1.w = acc[i][7] + b[c + 7];
            *(float4*)(out + gr * 128 + c + 0) = v0;
            *(float4*)(out + gr * 128 + c + 4) = v1;
        }
    }
}

// ---------------- fused edge kernel: online softmax + aggregate ----------
// one WARP per node; lane covers 4 dims (head = lane>>2)
__global__ void __launch_bounds__(128) k_layer(
    const float* __restrict__ att, const float* __restrict__ bias,
    float* __restrict__ out)
{
    const int warp = threadIdx.x >> 5;
    const int n    = blockIdx.x * 4 + warp;
    if (n >= N_NODES) return;
    const int lane = threadIdx.x & 31;
    const int c    = lane * 4;

    const float4 xr = *(const float4*)(g_xr + n * 128 + c);
    const float4 av = *(const float4*)(att + c);

    const int beg = g_start[n];
    const int end = g_start[n + 1];   // >= beg+1 (self loop guarantees)

    float  m = __int_as_float(0xFF800000);  // -inf
    float  s = 0.0f;
    float4 acc = make_float4(0.f, 0.f, 0.f, 0.f);

    // software pipeline: prefetch first edge row
    int    src = g_csr[beg];
    float4 v   = *(const float4*)(g_xl + src * 128 + c);

    for (int e = beg; e < end; e++) {
        float4 vcur = v;
        if (e + 1 < end) {
            int s2 = g_csr[e + 1];
            v = *(const float4*)(g_xl + s2 * 128 + c);
        }
        // leaky_relu(xl + xr) . att over this lane's 4 dims
        float zx = vcur.x + xr.x; zx = zx > 0.f ? zx : NEG_SLOPE * zx;
        float zy = vcur.y + xr.y; zy = zy > 0.f ? zy : NEG_SLOPE * zy;
        float zz = vcur.z + xr.z; zz = zz > 0.f ? zz : NEG_SLOPE * zz;
        float zw = vcur.w + xr.w; zw = zw > 0.f ? zw : NEG_SLOPE * zw;
        float w = zx * av.x;
        w = fmaf(zy, av.y, w);
        w = fmaf(zz, av.z, w);
        w = fmaf(zw, av.w, w);
        // reduce across the 4 lanes of this head
        w += __shfl_xor_sync(0xffffffffu, w, 1);
        w += __shfl_xor_sync(0xffffffffu, w, 2);
        // online softmax update; exp(-|d|) serves as both p and scale
        float d  = w - m;
        float q  = __expf(-fabsf(d));
        bool  nm = (d > 0.f);
        float p     = nm ? 1.0f : q;
        float scale = nm ? q : 1.0f;
        s = fmaf(s, scale, p);
        acc.x = fmaf(acc.x, scale, p * vcur.x);
        acc.y = fmaf(acc.y, scale, p * vcur.y);
        acc.z = fmaf(acc.z, scale, p * vcur.z);
        acc.w = fmaf(acc.w, scale, p * vcur.w);
        m = fmaxf(m, w);
    }

    const float inv = 1.0f / (s + 1e-16f);
    const float4 bi = *(const float4*)(bias + c);
    float4 o;
    o.x = acc.x * inv + bi.x;
    o.y = acc.y * inv + bi.y;
    o.z = acc.z * inv + bi.z;
    o.w = acc.w * inv + bi.w;
    *(float4*)(out + n * 128 + c) = o;
}

// ---------------- final head: out[c,l] = x[c*10+l] . w + b ---------------
__global__ void k_head(const float* __restrict__ xin, const float* __restrict__ w,
                       const float* __restrict__ bh, float* __restrict__ out)
{
    int gt   = blockIdx.x * blockDim.x + threadIdx.x;
    int warp = gt >> 5;
    int lane = gt & 31;
    if (warp >= (N_NODES / CHUNK) * NUM_LABELS) return;
    int c = warp / NUM_LABELS;
    int l = warp % NUM_LABELS;
    const float* row = xin + (c * CHUNK + l) * 128;
    float s = 0.0f;
    #pragma unroll
    for (int i = lane; i < 128; i += 32) s = fmaf(row[i], w[i], s);
    #pragma unroll
    for (int o = 16; o; o >>= 1) s += __shfl_down_sync(0xffffffffu, s, o);
    if (lane == 0) out[warp] = s + bh[0];
}

// ---------------- launch ---------------------------------------------------
extern "C" void kernel_launch(void* const* d_in, const int* in_sizes, int n_in,
                              void* d_out, int out_size)
{
    const float* x    = (const float*)d_in[0];
    const int*   eidx = (const int*)  d_in[1];
    // d_in[2] = nchunks (fixed = 8, chunk = 10; hardcoded)
    const float* Wl   = (const float*)d_in[3];
    const float* bl   = (const float*)d_in[4];
    const float* Wr   = (const float*)d_in[5];
    const float* br   = (const float*)d_in[6];
    const float* att  = (const float*)d_in[7];
    const float* bias = (const float*)d_in[8];
    const float* wh   = (const float*)d_in[9];
    const float* bh   = (const float*)d_in[10];
    float* out = (float*)d_out;

    float *bufA = nullptr, *bufB = nullptr;
    cudaGetSymbolAddress((void**)&bufA, g_bufA);
    cudaGetSymbolAddress((void**)&bufB, g_bufB);

    // CSR build (once per launch)
    k_detect_zero<<<(N_NODES + 255) / 256, 256>>>(eidx);
    k_extract<<<(E_TOT + 255) / 256, 256>>>(eidx);
    k_scan<<<1, 1024>>>();
    k_scatter<<<(E_TOT + 255) / 256, 256>>>();

    const float* cur = x;
    for (int l = 0; l < NUM_LAYERS; l++) {
        float* nxt = (l & 1) ? bufB : bufA;
        dim3 gg((N_NODES + 127) / 128, 2);
        k_gemm<<<gg, 256>>>(cur,
                            Wl + l * D_MODEL * D_MODEL, bl + l * D_MODEL,
                            Wr + l * D_MODEL * D_MODEL, br + l * D_MODEL);
        k_layer<<<(N_NODES + 3) / 4, 128>>>(att + l * NHEAD * HEAD_DIM,
                                            bias + l * D_MODEL, nxt);
        cur = nxt;
    }
    int nwarp = (N_NODES / CHUNK) * NUM_LABELS;  // 2000
    k_head<<<(nwarp * 32 + 255) / 256, 256>>>(cur, wh, bh, out);
}

// round 4
// speedup vs baseline: 1.7828x; 1.0056x over previous
#include <cuda_runtime.h>
#include <cuda_bf16.h>
#include <math_constants.h>

#define N_NODES   10000
#define N_EDGES   160000
#define E_TOT     170000      // edges + self loops
#define D_MODEL   128
#define NHEAD     8
#define HEAD_DIM  16
#define NUM_LAYERS 7
#define CHUNK     10          // NUM_LABELS + nchunks = 2 + 8
#define NUM_LABELS 2
#define NEG_SLOPE 0.2f

// ---------------- device scratch (no allocation allowed) ----------------
__device__ float g_bufA[N_NODES * D_MODEL];
__device__ float g_bufB[N_NODES * D_MODEL];
__device__ float g_xl[N_NODES * D_MODEL];
__device__ float g_xr[N_NODES * D_MODEL];
__device__ int   g_src[E_TOT];
__device__ int   g_dst[E_TOT];
__device__ int   g_cnt[N_NODES];
__device__ int   g_start[N_NODES + 1];
__device__ int   g_cursor[N_NODES];
__device__ int   g_csr[E_TOT];       // src node ids grouped by dst
__device__ int   g_is64;

// ---------------- packed f32x2 helpers (sm_103 FFMA2 path) ----------------
__device__ __forceinline__ unsigned long long pack2(float x) {
    unsigned long long r;
    asm("mov.b64 %0, {%1, %1};" : "=l"(r) : "f"(x));
    return r;
}
__device__ __forceinline__ void ffma2(unsigned long long& d,
                                      unsigned long long a,
                                      unsigned long long b) {
    asm("fma.rn.f32x2 %0, %1, %2, %0;" : "+l"(d) : "l"(a), "l"(b));
}
__device__ __forceinline__ unsigned long long addf32x2(unsigned long long a,
                                                       unsigned long long b) {
    unsigned long long r;
    asm("add.rn.f32x2 %0, %1, %2;" : "=l"(r) : "l"(a), "l"(b));
    return r;
}

// ------------- dtype detect (int32 vs int64) + zero counters -------------
__global__ void k_detect_zero(const int* __restrict__ e32) {
    int t = blockIdx.x * blockDim.x + threadIdx.x;
    if (t < N_NODES) g_cnt[t] = 0;
    if (blockIdx.x == 0) {
        __shared__ int nz;
        if (threadIdx.x == 0) nz = 0;
        __syncthreads();
        for (int i = threadIdx.x; i < 1024; i += blockDim.x)
            if (e32[2 * i + 1] != 0) nz = 1;
        __syncthreads();
        if (threadIdx.x == 0) g_is64 = (nz == 0) ? 1 : 0;
    }
}

// build src/dst (incl self loops) + histogram of dst
__global__ void k_extract(const int* __restrict__ e32) {
    int t = blockIdx.x * blockDim.x + threadIdx.x;
    if (t >= E_TOT) return;
    int s, d;
    if (t < N_EDGES) {
        if (g_is64) {
            s = e32[2 * t];
            d = e32[2 * (N_EDGES + t)];
        } else {
            s = e32[t];
            d = e32[N_EDGES + t];
        }
    } else {
        s = t - N_EDGES;
        d = s;
    }
    g_src[t] = s;
    g_dst[t] = d;
    atomicAdd(&g_cnt[d], 1);
}

// exclusive scan of g_cnt -> g_start / g_cursor. one block, 1024 threads.
__global__ void __launch_bounds__(1024) k_scan() {
    __shared__ int warpsum[32];
    const int t    = threadIdx.x;
    const int lane = t & 31;
    const int warp = t >> 5;
    const int base = t * 10;

    int local[10];
    int sum = 0;
    #pragma unroll
    for (int i = 0; i < 10; i++) {
        int idx = base + i;
        local[i] = (idx < N_NODES) ? g_cnt[idx] : 0;
        sum += local[i];
    }
    int incl = sum;
    #pragma unroll
    for (int off = 1; off < 32; off <<= 1) {
        int v = __shfl_up_sync(0xffffffffu, incl, off);
        if (lane >= off) incl += v;
    }
    if (lane == 31) warpsum[warp] = incl;
    __syncthreads();
    if (warp == 0) {
        int w = warpsum[lane];
        int wi = w;
        #pragma unroll
        for (int off = 1; off < 32; off <<= 1) {
            int v = __shfl_up_sync(0xffffffffu, wi, off);
            if (lane >= off) wi += v;
        }
        warpsum[lane] = wi - w;   // exclusive
    }
    __syncthreads();
    int run = warpsum[warp] + (incl - sum);
    #pragma unroll
    for (int i = 0; i < 10; i++) {
        int idx = base + i;
        if (idx < N_NODES) {
            g_start[idx]  = run;
            g_cursor[idx] = run;
        }
        run += local[i];
    }
    if (t == 0) g_start[N_NODES] = E_TOT;
}

__global__ void k_scatter() {
    int t = blockIdx.x * blockDim.x + threadIdx.x;
    if (t >= E_TOT) return;
    int d = g_dst[t];
    int pos = atomicAdd(&g_cursor[d], 1);
    g_csr[pos] = g_src[t];
}

// ---------------- fused GEMM: xl = X@Wl + bl ; xr = X@Wr + br -------------
// blockIdx.y: 0 -> (Wl,bl,g_xl) ; 1 -> (Wr,br,g_xr)
// 128x128 tile, BK=16, 256 threads, 8x8 micro-tile on packed f32x2 FFMA2
__global__ void __launch_bounds__(256) k_gemm(
    const float* __restrict__ X,
    const float* __restrict__ Wl, const float* __restrict__ bl,
    const float* __restrict__ Wr, const float* __restrict__ br)
{
    const float* W = blockIdx.y ? Wr : Wl;
    const float* b = blockIdx.y ? br : bl;
    float* out = blockIdx.y ? g_xr : g_xl;

    __shared__ float As[16][132];   // transposed A tile, padded
    __shared__ float Bs[16][128];

    const int tid  = threadIdx.x;
    const int tx   = tid & 15;      // 0..15 -> output cols tx*8
    const int ty   = tid >> 4;      // 0..15 -> output rows ty*8
    const int row0 = blockIdx.x * 128;

    unsigned long long acc2[8][4];  // 8 rows x 4 packed col-pairs
    #pragma unroll
    for (int i = 0; i < 8; i++)
        #pragma unroll
        for (int j = 0; j < 4; j++) acc2[i][j] = 0ull;

    for (int k0 = 0; k0 < 128; k0 += 16) {
        #pragma unroll
        for (int f = tid; f < 512; f += 256) {
            int r   = f >> 2;
            int kc4 = (f & 3) * 4;
            int gr  = row0 + r;
            float4 v = (gr < N_NODES)
                ? *(const float4*)(X + gr * 128 + k0 + kc4)
                : make_float4(0.f, 0.f, 0.f, 0.f);
            As[kc4 + 0][r] = v.x;
            As[kc4 + 1][r] = v.y;
            As[kc4 + 2][r] = v.z;
            As[kc4 + 3][r] = v.w;
        }
        #pragma unroll
        for (int f = tid; f < 512; f += 256) {
            int r  = f >> 5;
            int c4 = (f & 31) * 4;
            *(float4*)(&Bs[r][c4]) = *(const float4*)(W + (k0 + r) * 128 + c4);
        }
        __syncthreads();

        #pragma unroll
        for (int k = 0; k < 16; k++) {
            float a[8];
            *(float4*)(a + 0) = *(const float4*)(&As[k][ty * 8 + 0]);
            *(float4*)(a + 4) = *(const float4*)(&As[k][ty * 8 + 4]);
            ulonglong2 b01 = *(const ulonglong2*)(&Bs[k][tx * 8 + 0]);
            ulonglong2 b23 = *(const ulonglong2*)(&Bs[k][tx * 8 + 4]);
            unsigned long long bb0 = b01.x, bb1 = b01.y, bb2 = b23.x, bb3 = b23.y;
            #pragma unroll
            for (int i = 0; i < 8; i++) {
                unsigned long long ai = pack2(a[i]);
                ffma2(acc2[i][0], ai, bb0);
                ffma2(acc2[i][1], ai, bb1);
                ffma2(acc2[i][2], ai, bb2);
                ffma2(acc2[i][3], ai, bb3);
            }
        }
        __syncthreads();
    }

    const int c = tx * 8;
    ulonglong2 bp01 = *(const ulonglong2*)(b + c);      // packed bias pairs
    ulonglong2 bp23 = *(const ulonglong2*)(b + c + 4);
    #pragma unroll
    for (int i = 0; i < 8; i++) {
        int gr = row0 + ty * 8 + i;
        if (gr < N_NODES) {
            ulonglong2 o0, o1;
            o0.x = addf32x2(acc2[i][0], bp01.x);
            o0.y = addf32x2(acc2[i][1], bp01.y);
            o1.x = addf32x2(acc2[i][2], bp23.x);
            o1.y = addf32x2(acc2[i][3], bp23.y);
            *(ulonglong2*)(out + gr * 128 + c + 0) = o0;
            *(ulonglong2*)(out + gr * 128 + c + 4) = o1;
        }
    }
}

// ---------------- fused edge kernel: dual-stream online softmax ----------
// one WARP per node; lane covers 4 dims (head = lane>>2); edge list split
// into two independent streams to halve the serial softmax chain.
__global__ void __launch_bounds__(128) k_layer(
    const float* __restrict__ att, const float* __restrict__ bias,
    float* __restrict__ out)
{
    const int warp = threadIdx.x >> 5;
    const int n    = blockIdx.x * 4 + warp;
    if (n >= N_NODES) return;
    const int lane = threadIdx.x & 31;
    const int c    = lane * 4;

    const float4 xr = *(const float4*)(g_xr + n * 128 + c);
    const float4 av = *(const float4*)(att + c);

    const int beg = g_start[n];
    const int len = g_start[n + 1] - beg;   // >= 1 (self loop)
    const int lenA = (len + 1) >> 1;
    const int lenB = len - lenA;
    const int begB = beg + lenA;

    const float NINF = __int_as_float(0xFF800000);
    float  mA = NINF, sA = 0.0f;
    float  mB = NINF, sB = 0.0f;
    float4 accA = make_float4(0.f, 0.f, 0.f, 0.f);
    float4 accB = make_float4(0.f, 0.f, 0.f, 0.f);

    // prefetch first edge of each stream
    float4 vA = *(const float4*)(g_xl + g_csr[beg] * 128 + c);
    float4 vB;
    if (lenB > 0) vB = *(const float4*)(g_xl + g_csr[begB] * 128 + c);

    for (int i = 0; i < lenA; i++) {
        // ---- stream A ----
        {
            float4 cur = vA;
            if (i + 1 < lenA)
                vA = *(const float4*)(g_xl + g_csr[beg + i + 1] * 128 + c);
            float zx = cur.x + xr.x; zx = fmaxf(zx, NEG_SLOPE * zx);
            float zy = cur.y + xr.y; zy = fmaxf(zy, NEG_SLOPE * zy);
            float zz = cur.z + xr.z; zz = fmaxf(zz, NEG_SLOPE * zz);
            float zw = cur.w + xr.w; zw = fmaxf(zw, NEG_SLOPE * zw);
            float w = zx * av.x;
            w = fmaf(zy, av.y, w);
            w = fmaf(zz, av.z, w);
            w = fmaf(zw, av.w, w);
            w += __shfl_xor_sync(0xffffffffu, w, 1);
            w += __shfl_xor_sync(0xffffffffu, w, 2);
            float d  = w - mA;
            float q  = __expf(-fabsf(d));
            bool  nm = (d > 0.f);
            float p     = nm ? 1.0f : q;
            float scale = nm ? q : 1.0f;
            sA = fmaf(sA, scale, p);
            accA.x = fmaf(accA.x, scale, p * cur.x);
            accA.y = fmaf(accA.y, scale, p * cur.y);
            accA.z = fmaf(accA.z, scale, p * cur.z);
            accA.w = fmaf(accA.w, scale, p * cur.w);
            mA = fmaxf(mA, w);
        }
        // ---- stream B ----
        if (i < lenB) {
            float4 cur = vB;
            if (i + 1 < lenB)
                vB = *(const float4*)(g_xl + g_csr[begB + i + 1] * 128 + c);
            float zx = cur.x + xr.x; zx = fmaxf(zx, NEG_SLOPE * zx);
            float zy = cur.y + xr.y; zy = fmaxf(zy, NEG_SLOPE * zy);
            float zz = cur.z + xr.z; zz = fmaxf(zz, NEG_SLOPE * zz);
            float zw = cur.w + xr.w; zw = fmaxf(zw, NEG_SLOPE * zw);
            float w = zx * av.x;
            w = fmaf(zy, av.y, w);
            w = fmaf(zz, av.z, w);
            w = fmaf(zw, av.w, w);
            w += __shfl_xor_sync(0xffffffffu, w, 1);
            w += __shfl_xor_sync(0xffffffffu, w, 2);
            float d  = w - mB;
            float q  = __expf(-fabsf(d));
            bool  nm = (d > 0.f);
            float p     = nm ? 1.0f : q;
            float scale = nm ? q : 1.0f;
            sB = fmaf(sB, scale, p);
            accB.x = fmaf(accB.x, scale, p * cur.x);
            accB.y = fmaf(accB.y, scale, p * cur.y);
            accB.z = fmaf(accB.z, scale, p * cur.z);
            accB.w = fmaf(accB.w, scale, p * cur.w);
            mB = fmaxf(mB, w);
        }
    }

    // merge streams (expf(-inf)=0 handles empty B cleanly)
    float m  = fmaxf(mA, mB);
    float eA = __expf(mA - m);
    float eB = (lenB > 0) ? __expf(mB - m) : 0.0f;
    float s  = sA * eA + sB * eB;
    float4 acc;
    acc.x = accA.x * eA + accB.x * eB;
    acc.y = accA.y * eA + accB.y * eB;
    acc.z = accA.z * eA + accB.z * eB;
    acc.w = accA.w * eA + accB.w * eB;

    const float inv = 1.0f / (s + 1e-16f);
    const float4 bi = *(const float4*)(bias + c);
    float4 o;
    o.x = acc.x * inv + bi.x;
    o.y = acc.y * inv + bi.y;
    o.z = acc.z * inv + bi.z;
    o.w = acc.w * inv + bi.w;
    *(float4*)(out + n * 128 + c) = o;
}

// ---------------- final head: out[c,l] = x[c*10+l] . w + b ---------------
__global__ void k_head(const float* __restrict__ xin, const float* __restrict__ w,
                       const float* __restrict__ bh, float* __restrict__ out)
{
    int gt   = blockIdx.x * blockDim.x + threadIdx.x;
    int warp = gt >> 5;
    int lane = gt & 31;
    if (warp >= (N_NODES / CHUNK) * NUM_LABELS) return;
    int c = warp / NUM_LABELS;
    int l = warp % NUM_LABELS;
    const float* row = xin + (c * CHUNK + l) * 128;
    float s = 0.0f;
    #pragma unroll
    for (int i = lane; i < 128; i += 32) s = fmaf(row[i], w[i], s);
    #pragma unroll
    for (int o = 16; o; o >>= 1) s += __shfl_down_sync(0xffffffffu, s, o);
    if (lane == 0) out[warp] = s + bh[0];
}

// ---------------- launch ---------------------------------------------------
extern "C" void kernel_launch(void* const* d_in, const int* in_sizes, int n_in,
                              void* d_out, int out_size)
{
    const float* x    = (const float*)d_in[0];
    const int*   eidx = (const int*)  d_in[1];
    // d_in[2] = nchunks (fixed = 8, chunk = 10; hardcoded)
    const float* Wl   = (const float*)d_in[3];
    const float* bl   = (const float*)d_in[4];
    const float* Wr   = (const float*)d_in[5];
    const float* br   = (const float*)d_in[6];
    const float* att  = (const float*)d_in[7];
    const float* bias = (const float*)d_in[8];
    const float* wh   = (const float*)d_in[9];
    const float* bh   = (const float*)d_in[10];
    float* out = (float*)d_out;

    float *bufA = nullptr, *bufB = nullptr;
    cudaGetSymbolAddress((void**)&bufA, g_bufA);
    cudaGetSymbolAddress((void**)&bufB, g_bufB);

    // CSR build (once per launch)
    k_detect_zero<<<(N_NODES + 255) / 256, 256>>>(eidx);
    k_extract<<<(E_TOT + 255) / 256, 256>>>(eidx);
    k_scan<<<1, 1024>>>();
    k_scatter<<<(E_TOT + 255) / 256, 256>>>();

    const float* cur = x;
    for (int l = 0; l < NUM_LAYERS; l++) {
        float* nxt = (l & 1) ? bufB : bufA;
        dim3 gg((N_NODES + 127) / 128, 2);
        k_gemm<<<gg, 256>>>(cur,
                            Wl + l * D_MODEL * D_MODEL, bl + l * D_MODEL,
                            Wr + l * D_MODEL * D_MODEL, br + l * D_MODEL);
        k_layer<<<(N_NODES + 3) / 4, 128>>>(att + l * NHEAD * HEAD_DIM,
                                            bias + l * D_MODEL, nxt);
        cur = nxt;
    }
    int nwarp = (N_NODES / CHUNK) * NUM_LABELS;  // 2000
    k_head<<<(nwarp * 32 + 255) / 256, 256>>>(cur, wh, bh, out);
}